// round 6
// baseline (speedup 1.0000x reference)
#include <cuda_runtime.h>
#include <cuda_fp16.h>

#define HH 512
#define WW 512
#define CC 128
#define NPTS 524288
#define PLANE_ELEMS (CC * HH * WW)
#define NBINS 256      // uv tiles: 16x16 grid of 32x32-texel tiles
#define BINPAD 32      // pad counters to 128B (one L2 line per bin)

#define TRANS_BLOCKS (2 * HH * (WW / 32))  // 16384
#define SETUP_BLOCKS (NPTS / 256)          // 2048

// Transposed fp16 planes [H][W][C].
__device__ __align__(16) __half g_uvT[PLANE_ELEMS];
__device__ __align__(16) __half g_stT[PLANE_ELEMS];
// Per-point params (original point order): {bases, uv weights, st weights}.
__device__ __align__(16) uint4 g_params[NPTS * 3];
__device__ unsigned char g_key[NPTS];
__device__ int g_pid[NPTS];   // sorted order -> original point id
__device__ __align__(128) int g_hist[NBINS * BINPAD];
__device__ __align__(128) int g_cursor[NBINS * BINPAD];

__device__ __forceinline__ unsigned packw(float w) {
    __half2 h = __float2half2_rn(w);
    return *(unsigned*)&h;
}

// ---------------------------------------------------------------------------
// Kernel 0: zero padded histogram (graph replays need this every launch).
// ---------------------------------------------------------------------------
__global__ void zero_kernel() {
    g_hist[blockIdx.x * 256 + threadIdx.x] = 0;
}

// ---------------------------------------------------------------------------
// Kernel 1 (fused): transpose f32[C,H,W] -> f16[H,W,C]  +  per-point setup
// (params + bin key + padded histogram RED). Transpose is DRAM-bound,
// setup is latency-bound -> they overlap in one grid.
// ---------------------------------------------------------------------------
__global__ __launch_bounds__(256) void prep_kernel(
    const float* __restrict__ uv, const float* __restrict__ st,
    const float4* __restrict__ xs, const float* __restrict__ b) {
    const int bid = blockIdx.x;
    const int tid = threadIdx.x;

    if (bid < TRANS_BLOCKS) {
        __shared__ float tile[CC][33];
        const int plane = bid >> 13;
        const int rem = bid & 8191;
        const int y = rem >> 4;
        const int x0 = (rem & 15) * 32;
        const int tx = tid & 31;
        const int ty = tid >> 5;

        const float* src = plane ? st : uv;
        __half* dst = plane ? g_stT : g_uvT;

        #pragma unroll
        for (int i = 0; i < 16; i++) {
            const int c = ty + i * 8;
            tile[c][tx] = src[c * (HH * WW) + y * WW + x0 + tx];
        }
        __syncthreads();

        const int c2 = (tid & 63) * 2;
        const int xb = tid >> 6;
        #pragma unroll
        for (int i = 0; i < 8; i++) {
            const int xi = xb + i * 4;
            __half2 v = __floats2half2_rn(tile[c2][xi], tile[c2 + 1][xi]);
            *(__half2*)(dst + (size_t)(y * WW + x0 + xi) * CC + c2) = v;
        }
    } else {
        const int i = (bid - TRANS_BLOCKS) * 256 + tid;
        const float4 p = xs[i];

        const float ixu = __fdividef(p.x - b[0], b[4] - b[0]) * (WW - 1);
        const float iyu = __fdividef(p.y - b[1], b[5] - b[1]) * (HH - 1);
        const float ixs = __fdividef(p.z - b[2], b[6] - b[2]) * (WW - 1);
        const float iys = __fdividef(p.w - b[3], b[7] - b[3]) * (HH - 1);

        const int xu0 = min(max(__float2int_rd(ixu), 0), WW - 2);
        const int yu0 = min(max(__float2int_rd(iyu), 0), HH - 2);
        const int xs0 = min(max(__float2int_rd(ixs), 0), WW - 2);
        const int ys0 = min(max(__float2int_rd(iys), 0), HH - 2);

        const float wxu = ixu - (float)xu0, wyu = iyu - (float)yu0;
        const float wxs = ixs - (float)xs0, wys = iys - (float)ys0;

        uint4 A;
        A.x = (unsigned)((yu0 * WW + xu0) * CC);
        A.y = (unsigned)((ys0 * WW + xs0) * CC);
        A.z = 0; A.w = 0;

        uint4 WU;
        WU.x = packw((1.f - wxu) * (1.f - wyu));
        WU.y = packw(wxu * (1.f - wyu));
        WU.z = packw((1.f - wxu) * wyu);
        WU.w = packw(wxu * wyu);

        uint4 WS;
        WS.x = packw((1.f - wxs) * (1.f - wys));
        WS.y = packw(wxs * (1.f - wys));
        WS.z = packw((1.f - wxs) * wys);
        WS.w = packw(wxs * wys);

        g_params[3 * i] = A;
        g_params[3 * i + 1] = WU;
        g_params[3 * i + 2] = WS;

        const int key = (yu0 >> 5) * 16 + (xu0 >> 5);
        g_key[i] = (unsigned char)key;
        atomicAdd(&g_hist[key * BINPAD], 1);  // RED, one L2 line per bin
    }
}

// ---------------------------------------------------------------------------
// Kernel 2: exclusive scan of 256-bin padded histogram (one block).
// ---------------------------------------------------------------------------
__global__ void scan_kernel() {
    __shared__ int s[NBINS];
    const int t = threadIdx.x;
    const int v = g_hist[t * BINPAD];
    s[t] = v;
    __syncthreads();
    #pragma unroll
    for (int d = 1; d < NBINS; d <<= 1) {
        const int u = (t >= d) ? s[t - d] : 0;
        __syncthreads();
        s[t] += u;
        __syncthreads();
    }
    g_cursor[t * BINPAD] = s[t] - v;  // exclusive prefix
}

// ---------------------------------------------------------------------------
// Kernel 3: scatter POINT IDS ONLY into bin-sorted order.
// Block-aggregated atomics: smem rank, one global atomic per (bin, block).
// ---------------------------------------------------------------------------
__global__ __launch_bounds__(256) void scatter_kernel() {
    __shared__ int loc[NBINS];
    __shared__ int base[NBINS];
    const int tid = threadIdx.x;
    const int i = blockIdx.x * 256 + tid;

    loc[tid] = 0;
    __syncthreads();

    const int key = g_key[i];
    const int rank = atomicAdd_block(&loc[key], 1);
    __syncthreads();

    const int cnt = loc[tid];
    if (cnt > 0) base[tid] = atomicAdd(&g_cursor[tid * BINPAD], cnt);
    __syncthreads();

    g_pid[base[key] + rank] = i;
}

// ---------------------------------------------------------------------------
// Kernel 4: 16 lanes per point; lane = 8 channels via one uint4 per corner.
// Sorted order via pid indirection; params stay in original layout.
// ---------------------------------------------------------------------------
__device__ __forceinline__ __half2 u2h(unsigned u) { return *(__half2*)&u; }

__global__ __launch_bounds__(256) void point_kernel(float* __restrict__ out) {
    const int warp = (blockIdx.x * 256 + threadIdx.x) >> 5;
    const int lane = threadIdx.x & 31;
    const int sub = lane >> 4;
    const int gl = lane & 15;
    const int sp = warp * 2 + sub;  // sorted slot

    const int pid = g_pid[sp];  // broadcast across the 16-lane group

    const uint4 A  = g_params[3 * pid];
    const uint4 WU = g_params[3 * pid + 1];
    const uint4 WS = g_params[3 * pid + 2];

    const __half* U = g_uvT + A.x + gl * 8;
    const __half* S = g_stT + A.y + gl * 8;

    const uint4 u00 = *(const uint4*)(U);
    const uint4 u01 = *(const uint4*)(U + CC);
    const uint4 u10 = *(const uint4*)(U + WW * CC);
    const uint4 u11 = *(const uint4*)(U + WW * CC + CC);
    const uint4 s00 = *(const uint4*)(S);
    const uint4 s01 = *(const uint4*)(S + CC);
    const uint4 s10 = *(const uint4*)(S + WW * CC);
    const uint4 s11 = *(const uint4*)(S + WW * CC + CC);

    __half2 au[4], av[4];
    {
        const __half2 w00 = u2h(WU.x), w01 = u2h(WU.y), w10 = u2h(WU.z), w11 = u2h(WU.w);
        const __half2* p00 = (const __half2*)&u00;
        const __half2* p01 = (const __half2*)&u01;
        const __half2* p10 = (const __half2*)&u10;
        const __half2* p11 = (const __half2*)&u11;
        #pragma unroll
        for (int j = 0; j < 4; j++) {
            __half2 a = __hmul2(p00[j], w00);
            a = __hfma2(p01[j], w01, a);
            a = __hfma2(p10[j], w10, a);
            au[j] = __hfma2(p11[j], w11, a);
        }
    }
    {
        const __half2 w00 = u2h(WS.x), w01 = u2h(WS.y), w10 = u2h(WS.z), w11 = u2h(WS.w);
        const __half2* p00 = (const __half2*)&s00;
        const __half2* p01 = (const __half2*)&s01;
        const __half2* p10 = (const __half2*)&s10;
        const __half2* p11 = (const __half2*)&s11;
        #pragma unroll
        for (int j = 0; j < 4; j++) {
            __half2 a = __hmul2(p00[j], w00);
            a = __hfma2(p01[j], w01, a);
            a = __hfma2(p10[j], w10, a);
            av[j] = __hfma2(p11[j], w11, a);
        }
    }

    float f[8];
    #pragma unroll
    for (int j = 0; j < 4; j++) {
        const float2 t = __half22float2(__hmul2(au[j], av[j]));
        f[2 * j] = t.x;
        f[2 * j + 1] = t.y;
    }

    #pragma unroll
    for (int s = 8; s >= 1; s >>= 1) {
        #pragma unroll
        for (int j = 0; j < 8; j++)
            f[j] += __shfl_xor_sync(0xffffffffu, f[j], s);
    }

    if (gl == 0) {
        float4 o0, o1;
        o0.x = 1.f / (1.f + __expf(-f[0]));
        o0.y = 1.f / (1.f + __expf(-f[1]));
        o0.z = 1.f / (1.f + __expf(-f[2]));
        o0.w = 1.f / (1.f + __expf(-f[3]));
        o1.x = 1.f / (1.f + __expf(-f[4]));
        o1.y = 1.f / (1.f + __expf(-f[5]));
        o1.z = 1.f / (1.f + __expf(-f[6]));
        o1.w = 1.f / (1.f + __expf(-f[7]));
        __stcs(&((float4*)out)[pid * 2], o0);
        __stcs(&((float4*)out)[pid * 2 + 1], o1);
    }
}

// ---------------------------------------------------------------------------
extern "C" void kernel_launch(void* const* d_in, const int* in_sizes, int n_in,
                              void* d_out, int out_size) {
    const float* x = (const float*)d_in[0];
    const float* uv = (const float*)d_in[1];
    const float* st = (const float*)d_in[2];
    const float* bounds = (const float*)d_in[3];
    float* out = (float*)d_out;

    zero_kernel<<<(NBINS * BINPAD) / 256, 256>>>();
    prep_kernel<<<TRANS_BLOCKS + SETUP_BLOCKS, 256>>>(
        uv, st, (const float4*)x, bounds);
    scan_kernel<<<1, NBINS>>>();
    scatter_kernel<<<NPTS / 256, 256>>>();
    point_kernel<<<NPTS / 16, 256>>>(out);
}

// round 7
// speedup vs baseline: 1.0625x; 1.0625x over previous
#include <cuda_runtime.h>
#include <cuda_fp16.h>

#define HH 512
#define WW 512
#define CC 128
#define NPTS 524288
#define PLANE_ELEMS (CC * HH * WW)
#define NBINS 256      // uv tiles: 16x16 grid of 32x32-texel tiles
#define BINPAD 32      // pad counters to 128B (one L2 line per bin)

#define TRANS_BLOCKS (2 * HH * (WW / 32))  // 16384
#define SETUP_BLOCKS (NPTS / 256)          // 2048

// Transposed fp16 planes [H][W][C].
__device__ __align__(16) __half g_uvT[PLANE_ELEMS];
__device__ __align__(16) __half g_stT[PLANE_ELEMS];
// Per-point 32B records, unsorted then sorted:
//   rec0: {baseUV, baseST, h2(w00u,w01u), h2(w10u,w11u)}
//   rec1: {h2(w00s,w01s), h2(w10s,w11s), pid, 0}
__device__ __align__(16) uint4 g_rec[NPTS * 2];
__device__ __align__(16) uint4 g_srec[NPTS * 2];
__device__ unsigned char g_key[NPTS];
__device__ __align__(128) int g_hist[NBINS * BINPAD];
__device__ __align__(128) int g_cursor[NBINS * BINPAD];

__device__ __forceinline__ unsigned packw2(float a, float b) {
    __half2 h = __floats2half2_rn(a, b);
    return *(unsigned*)&h;
}

// ---------------------------------------------------------------------------
// Kernel 0: zero padded histogram (graph replays).
// ---------------------------------------------------------------------------
__global__ void zero_kernel() {
    g_hist[blockIdx.x * 256 + threadIdx.x] = 0;
}

// ---------------------------------------------------------------------------
// Kernel 1 (fused): transpose f32[C,H,W] -> f16[H,W,C]  +  per-point setup
// (record + bin key + padded histogram RED).
// ---------------------------------------------------------------------------
__global__ __launch_bounds__(256) void prep_kernel(
    const float* __restrict__ uv, const float* __restrict__ st,
    const float4* __restrict__ xs, const float* __restrict__ b) {
    const int bid = blockIdx.x;
    const int tid = threadIdx.x;

    if (bid < TRANS_BLOCKS) {
        __shared__ float tile[CC][33];
        const int plane = bid >> 13;
        const int rem = bid & 8191;
        const int y = rem >> 4;
        const int x0 = (rem & 15) * 32;
        const int tx = tid & 31;
        const int ty = tid >> 5;

        const float* src = plane ? st : uv;
        __half* dst = plane ? g_stT : g_uvT;

        #pragma unroll
        for (int i = 0; i < 16; i++) {
            const int c = ty + i * 8;
            tile[c][tx] = src[c * (HH * WW) + y * WW + x0 + tx];
        }
        __syncthreads();

        const int c2 = (tid & 63) * 2;
        const int xb = tid >> 6;
        #pragma unroll
        for (int i = 0; i < 8; i++) {
            const int xi = xb + i * 4;
            __half2 v = __floats2half2_rn(tile[c2][xi], tile[c2 + 1][xi]);
            *(__half2*)(dst + (size_t)(y * WW + x0 + xi) * CC + c2) = v;
        }
    } else {
        const int i = (bid - TRANS_BLOCKS) * 256 + tid;
        const float4 p = xs[i];

        const float ixu = __fdividef(p.x - b[0], b[4] - b[0]) * (WW - 1);
        const float iyu = __fdividef(p.y - b[1], b[5] - b[1]) * (HH - 1);
        const float ixs = __fdividef(p.z - b[2], b[6] - b[2]) * (WW - 1);
        const float iys = __fdividef(p.w - b[3], b[7] - b[3]) * (HH - 1);

        const int xu0 = min(max(__float2int_rd(ixu), 0), WW - 2);
        const int yu0 = min(max(__float2int_rd(iyu), 0), HH - 2);
        const int xs0 = min(max(__float2int_rd(ixs), 0), WW - 2);
        const int ys0 = min(max(__float2int_rd(iys), 0), HH - 2);

        const float wxu = ixu - (float)xu0, wyu = iyu - (float)yu0;
        const float wxs = ixs - (float)xs0, wys = iys - (float)ys0;

        uint4 r0, r1;
        r0.x = (unsigned)((yu0 * WW + xu0) * CC);
        r0.y = (unsigned)((ys0 * WW + xs0) * CC);
        r0.z = packw2((1.f - wxu) * (1.f - wyu), wxu * (1.f - wyu));
        r0.w = packw2((1.f - wxu) * wyu, wxu * wyu);
        r1.x = packw2((1.f - wxs) * (1.f - wys), wxs * (1.f - wys));
        r1.y = packw2((1.f - wxs) * wys, wxs * wys);
        r1.z = (unsigned)i;
        r1.w = 0;

        g_rec[2 * i] = r0;
        g_rec[2 * i + 1] = r1;

        const int key = (yu0 >> 5) * 16 + (xu0 >> 5);
        g_key[i] = (unsigned char)key;
        atomicAdd(&g_hist[key * BINPAD], 1);  // RED, one L2 line per bin
    }
}

// ---------------------------------------------------------------------------
// Kernel 2: exclusive scan of 256-bin padded histogram (one block).
// ---------------------------------------------------------------------------
__global__ void scan_kernel() {
    __shared__ int s[NBINS];
    const int t = threadIdx.x;
    const int v = g_hist[t * BINPAD];
    s[t] = v;
    __syncthreads();
    #pragma unroll
    for (int d = 1; d < NBINS; d <<= 1) {
        const int u = (t >= d) ? s[t - d] : 0;
        __syncthreads();
        s[t] += u;
        __syncthreads();
    }
    g_cursor[t * BINPAD] = s[t] - v;  // exclusive prefix
}

// ---------------------------------------------------------------------------
// Kernel 3: scatter 32B records into bin-sorted order.
// Block-aggregated atomics: smem rank, one global atomic per (bin, block).
// ---------------------------------------------------------------------------
__global__ __launch_bounds__(256) void scatter_kernel() {
    __shared__ int loc[NBINS];
    __shared__ int base[NBINS];
    const int tid = threadIdx.x;
    const int i = blockIdx.x * 256 + tid;

    loc[tid] = 0;
    __syncthreads();

    const int key = g_key[i];
    const int rank = atomicAdd_block(&loc[key], 1);
    __syncthreads();

    const int cnt = loc[tid];
    if (cnt > 0) base[tid] = atomicAdd(&g_cursor[tid * BINPAD], cnt);
    __syncthreads();

    const int dst = base[key] + rank;
    g_srec[2 * dst] = g_rec[2 * i];
    g_srec[2 * dst + 1] = g_rec[2 * i + 1];
}

// ---------------------------------------------------------------------------
// Kernel 4: 16 lanes per point; lane = 8 channels via one uint4 per corner.
// Contiguous sorted records; splat corner weights from packed half2 pairs.
// ---------------------------------------------------------------------------
__device__ __forceinline__ __half2 u2h(unsigned u) { return *(__half2*)&u; }

__global__ __launch_bounds__(256) void point_kernel(float* __restrict__ out) {
    const int warp = (blockIdx.x * 256 + threadIdx.x) >> 5;
    const int lane = threadIdx.x & 31;
    const int sub = lane >> 4;
    const int gl = lane & 15;
    const int sp = warp * 2 + sub;  // sorted slot

    const uint4 r0 = __ldcs(&g_srec[2 * sp]);
    const uint4 r1 = __ldcs(&g_srec[2 * sp + 1]);
    const int pid = (int)r1.z;

    const __half* U = g_uvT + r0.x + gl * 8;
    const __half* S = g_stT + r0.y + gl * 8;

    const uint4 u00 = *(const uint4*)(U);
    const uint4 u01 = *(const uint4*)(U + CC);
    const uint4 u10 = *(const uint4*)(U + WW * CC);
    const uint4 u11 = *(const uint4*)(U + WW * CC + CC);
    const uint4 s00 = *(const uint4*)(S);
    const uint4 s01 = *(const uint4*)(S + CC);
    const uint4 s10 = *(const uint4*)(S + WW * CC);
    const uint4 s11 = *(const uint4*)(S + WW * CC + CC);

    __half2 au[4], av[4];
    {
        const __half2 wp = u2h(r0.z), wq = u2h(r0.w);
        const __half2 w00 = __low2half2(wp), w01 = __high2half2(wp);
        const __half2 w10 = __low2half2(wq), w11 = __high2half2(wq);
        const __half2* p00 = (const __half2*)&u00;
        const __half2* p01 = (const __half2*)&u01;
        const __half2* p10 = (const __half2*)&u10;
        const __half2* p11 = (const __half2*)&u11;
        #pragma unroll
        for (int j = 0; j < 4; j++) {
            __half2 a = __hmul2(p00[j], w00);
            a = __hfma2(p01[j], w01, a);
            a = __hfma2(p10[j], w10, a);
            au[j] = __hfma2(p11[j], w11, a);
        }
    }
    {
        const __half2 wp = u2h(r1.x), wq = u2h(r1.y);
        const __half2 w00 = __low2half2(wp), w01 = __high2half2(wp);
        const __half2 w10 = __low2half2(wq), w11 = __high2half2(wq);
        const __half2* p00 = (const __half2*)&s00;
        const __half2* p01 = (const __half2*)&s01;
        const __half2* p10 = (const __half2*)&s10;
        const __half2* p11 = (const __half2*)&s11;
        #pragma unroll
        for (int j = 0; j < 4; j++) {
            __half2 a = __hmul2(p00[j], w00);
            a = __hfma2(p01[j], w01, a);
            a = __hfma2(p10[j], w10, a);
            av[j] = __hfma2(p11[j], w11, a);
        }
    }

    float f[8];
    #pragma unroll
    for (int j = 0; j < 4; j++) {
        const float2 t = __half22float2(__hmul2(au[j], av[j]));
        f[2 * j] = t.x;
        f[2 * j + 1] = t.y;
    }

    #pragma unroll
    for (int s = 8; s >= 1; s >>= 1) {
        #pragma unroll
        for (int j = 0; j < 8; j++)
            f[j] += __shfl_xor_sync(0xffffffffu, f[j], s);
    }

    if (gl == 0) {
        float4 o0, o1;
        o0.x = 1.f / (1.f + __expf(-f[0]));
        o0.y = 1.f / (1.f + __expf(-f[1]));
        o0.z = 1.f / (1.f + __expf(-f[2]));
        o0.w = 1.f / (1.f + __expf(-f[3]));
        o1.x = 1.f / (1.f + __expf(-f[4]));
        o1.y = 1.f / (1.f + __expf(-f[5]));
        o1.z = 1.f / (1.f + __expf(-f[6]));
        o1.w = 1.f / (1.f + __expf(-f[7]));
        __stcs(&((float4*)out)[pid * 2], o0);
        __stcs(&((float4*)out)[pid * 2 + 1], o1);
    }
}

// ---------------------------------------------------------------------------
extern "C" void kernel_launch(void* const* d_in, const int* in_sizes, int n_in,
                              void* d_out, int out_size) {
    const float* x = (const float*)d_in[0];
    const float* uv = (const float*)d_in[1];
    const float* st = (const float*)d_in[2];
    const float* bounds = (const float*)d_in[3];
    float* out = (float*)d_out;

    zero_kernel<<<(NBINS * BINPAD) / 256, 256>>>();
    prep_kernel<<<TRANS_BLOCKS + SETUP_BLOCKS, 256>>>(
        uv, st, (const float4*)x, bounds);
    scan_kernel<<<1, NBINS>>>();
    scatter_kernel<<<NPTS / 256, 256>>>();
    point_kernel<<<NPTS / 16, 256>>>(out);
}

// round 8
// speedup vs baseline: 1.3182x; 1.2407x over previous
#include <cuda_runtime.h>
#include <cuda_fp16.h>

#define HH 512
#define WW 512
#define CC 128
#define NPTS 524288
#define PLANE_ELEMS (CC * HH * WW)

#define TRANS_BLOCKS (2 * HH * (WW / 32))  // 16384
#define SETUP_BLOCKS (NPTS / 256)          // 2048

// Transposed fp16 planes [H][W][C] (channel-last).
__device__ __align__(16) __half g_uvT[PLANE_ELEMS];
__device__ __align__(16) __half g_stT[PLANE_ELEMS];
// 32B per-point record: {baseUV, baseST, uvW01, uvW23} {stW01, stW23, -, -}
__device__ __align__(16) uint4 g_rec[NPTS * 2];
// Partial sums from pass A (8 floats per point).
__device__ __align__(16) float g_partial[NPTS * 8];

__device__ __forceinline__ unsigned packw2(float a, float b) {
    __half2 h = __floats2half2_rn(a, b);
    return *(unsigned*)&h;
}
__device__ __forceinline__ __half2 u2h(unsigned u) { return *(__half2*)&u; }

// ---------------------------------------------------------------------------
// Kernel 1 (fused): transpose f32[C,H,W] -> f16[H,W,C]  +  per-point setup.
// Transpose is DRAM-bound, setup latency-bound -> overlap in one grid.
// ---------------------------------------------------------------------------
__global__ __launch_bounds__(256) void prep_kernel(
    const float* __restrict__ uv, const float* __restrict__ st,
    const float4* __restrict__ xs, const float* __restrict__ b) {
    const int bid = blockIdx.x;
    const int tid = threadIdx.x;

    if (bid < TRANS_BLOCKS) {
        __shared__ float tile[CC][33];
        const int plane = bid >> 13;
        const int rem = bid & 8191;
        const int y = rem >> 4;
        const int x0 = (rem & 15) * 32;
        const int tx = tid & 31;
        const int ty = tid >> 5;

        const float* src = plane ? st : uv;
        __half* dst = plane ? g_stT : g_uvT;

        #pragma unroll
        for (int i = 0; i < 16; i++) {
            const int c = ty + i * 8;
            tile[c][tx] = src[c * (HH * WW) + y * WW + x0 + tx];
        }
        __syncthreads();

        const int c2 = (tid & 63) * 2;
        const int xb = tid >> 6;
        #pragma unroll
        for (int i = 0; i < 8; i++) {
            const int xi = xb + i * 4;
            __half2 v = __floats2half2_rn(tile[c2][xi], tile[c2 + 1][xi]);
            *(__half2*)(dst + (size_t)(y * WW + x0 + xi) * CC + c2) = v;
        }
    } else {
        const int i = (bid - TRANS_BLOCKS) * 256 + tid;
        const float4 p = xs[i];

        const float ixu = __fdividef(p.x - b[0], b[4] - b[0]) * (WW - 1);
        const float iyu = __fdividef(p.y - b[1], b[5] - b[1]) * (HH - 1);
        const float ixs = __fdividef(p.z - b[2], b[6] - b[2]) * (WW - 1);
        const float iys = __fdividef(p.w - b[3], b[7] - b[3]) * (HH - 1);

        const int xu0 = min(max(__float2int_rd(ixu), 0), WW - 2);
        const int yu0 = min(max(__float2int_rd(iyu), 0), HH - 2);
        const int xs0 = min(max(__float2int_rd(ixs), 0), WW - 2);
        const int ys0 = min(max(__float2int_rd(iys), 0), HH - 2);

        const float wxu = ixu - (float)xu0, wyu = iyu - (float)yu0;
        const float wxs = ixs - (float)xs0, wys = iys - (float)ys0;

        uint4 r0, r1;
        r0.x = (unsigned)((yu0 * WW + xu0) * CC);
        r0.y = (unsigned)((ys0 * WW + xs0) * CC);
        r0.z = packw2((1.f - wxu) * (1.f - wyu), wxu * (1.f - wyu));
        r0.w = packw2((1.f - wxu) * wyu, wxu * wyu);
        r1.x = packw2((1.f - wxs) * (1.f - wys), wxs * (1.f - wys));
        r1.y = packw2((1.f - wxs) * wys, wxs * wys);
        r1.z = 0;
        r1.w = 0;

        g_rec[2 * i] = r0;
        g_rec[2 * i + 1] = r1;
    }
}

// ---------------------------------------------------------------------------
// Pass kernel: 8 lanes per point, lane gl handles channels CHOFF + 8*gl
// (one uint4 per corner). Per-pass plane footprint = 64MB -> L2 resident.
// FIRST pass writes partials; second pass adds, applies sigmoid, stores out.
// ---------------------------------------------------------------------------
template <int CHOFF, bool FIRST>
__global__ __launch_bounds__(256) void pass_kernel(float* __restrict__ out) {
    const int tid = blockIdx.x * 256 + threadIdx.x;
    const int p = tid >> 3;         // point (4 per warp)
    const int gl = threadIdx.x & 7; // lane in 8-lane group

    const uint4 r0 = __ldcs(&g_rec[2 * p]);
    const uint4 r1 = __ldcs(&g_rec[2 * p + 1]);

    const __half* U = g_uvT + r0.x + CHOFF + gl * 8;
    const __half* S = g_stT + r0.y + CHOFF + gl * 8;

    // 8 independent 16B loads.
    const uint4 u00 = *(const uint4*)(U);
    const uint4 u01 = *(const uint4*)(U + CC);
    const uint4 u10 = *(const uint4*)(U + WW * CC);
    const uint4 u11 = *(const uint4*)(U + WW * CC + CC);
    const uint4 s00 = *(const uint4*)(S);
    const uint4 s01 = *(const uint4*)(S + CC);
    const uint4 s10 = *(const uint4*)(S + WW * CC);
    const uint4 s11 = *(const uint4*)(S + WW * CC + CC);

    __half2 au[4], av[4];
    {
        const __half2 wp = u2h(r0.z), wq = u2h(r0.w);
        const __half2 w00 = __low2half2(wp), w01 = __high2half2(wp);
        const __half2 w10 = __low2half2(wq), w11 = __high2half2(wq);
        const __half2* p00 = (const __half2*)&u00;
        const __half2* p01 = (const __half2*)&u01;
        const __half2* p10 = (const __half2*)&u10;
        const __half2* p11 = (const __half2*)&u11;
        #pragma unroll
        for (int j = 0; j < 4; j++) {
            __half2 a = __hmul2(p00[j], w00);
            a = __hfma2(p01[j], w01, a);
            a = __hfma2(p10[j], w10, a);
            au[j] = __hfma2(p11[j], w11, a);
        }
    }
    {
        const __half2 wp = u2h(r1.x), wq = u2h(r1.y);
        const __half2 w00 = __low2half2(wp), w01 = __high2half2(wp);
        const __half2 w10 = __low2half2(wq), w11 = __high2half2(wq);
        const __half2* p00 = (const __half2*)&s00;
        const __half2* p01 = (const __half2*)&s01;
        const __half2* p10 = (const __half2*)&s10;
        const __half2* p11 = (const __half2*)&s11;
        #pragma unroll
        for (int j = 0; j < 4; j++) {
            __half2 a = __hmul2(p00[j], w00);
            a = __hfma2(p01[j], w01, a);
            a = __hfma2(p10[j], w10, a);
            av[j] = __hfma2(p11[j], w11, a);
        }
    }

    // Products -> f32; lane gl holds outputs j = 0..7 for component CHOFF/8+gl.
    float f[8];
    #pragma unroll
    for (int j = 0; j < 4; j++) {
        const float2 t = __half22float2(__hmul2(au[j], av[j]));
        f[2 * j] = t.x;
        f[2 * j + 1] = t.y;
    }

    // Sum over the 8 lanes of the group (8 components this pass).
    #pragma unroll
    for (int s = 4; s >= 1; s >>= 1) {
        #pragma unroll
        for (int j = 0; j < 8; j++)
            f[j] += __shfl_xor_sync(0xffffffffu, f[j], s);
    }

    if (gl == 0) {
        if (FIRST) {
            float4 a = {f[0], f[1], f[2], f[3]};
            float4 b = {f[4], f[5], f[6], f[7]};
            __stcs(&((float4*)g_partial)[p * 2], a);
            __stcs(&((float4*)g_partial)[p * 2 + 1], b);
        } else {
            const float4 a = __ldcs(&((const float4*)g_partial)[p * 2]);
            const float4 b = __ldcs(&((const float4*)g_partial)[p * 2 + 1]);
            float4 o0, o1;
            o0.x = 1.f / (1.f + __expf(-(f[0] + a.x)));
            o0.y = 1.f / (1.f + __expf(-(f[1] + a.y)));
            o0.z = 1.f / (1.f + __expf(-(f[2] + a.z)));
            o0.w = 1.f / (1.f + __expf(-(f[3] + a.w)));
            o1.x = 1.f / (1.f + __expf(-(f[4] + b.x)));
            o1.y = 1.f / (1.f + __expf(-(f[5] + b.y)));
            o1.z = 1.f / (1.f + __expf(-(f[6] + b.z)));
            o1.w = 1.f / (1.f + __expf(-(f[7] + b.w)));
            __stcs(&((float4*)out)[p * 2], o0);
            __stcs(&((float4*)out)[p * 2 + 1], o1);
        }
    }
}

// ---------------------------------------------------------------------------
extern "C" void kernel_launch(void* const* d_in, const int* in_sizes, int n_in,
                              void* d_out, int out_size) {
    const float* x = (const float*)d_in[0];
    const float* uv = (const float*)d_in[1];
    const float* st = (const float*)d_in[2];
    const float* bounds = (const float*)d_in[3];
    float* out = (float*)d_out;

    prep_kernel<<<TRANS_BLOCKS + SETUP_BLOCKS, 256>>>(
        uv, st, (const float4*)x, bounds);

    // 32 points per block (8 lanes/point).
    pass_kernel<0, true><<<NPTS / 32, 256>>>(out);
    pass_kernel<64, false><<<NPTS / 32, 256>>>(out);
}